// round 10
// baseline (speedup 1.0000x reference)
#include <cuda_runtime.h>
#include <stdint.h>

// Problem constants
#define Bb    32768
#define Ll    7
#define Tt    6
#define Hh    256
#define TS    5                 // only edges t=0..4 are live
#define MROWS (Bb * TS)         // 163840
#define MCTX  (Bb * Ll)         // 229376

// ---------------- device scratch (static, allocation-free) ----------------
__device__ float g_Edge[(size_t)MROWS * Hh];
__device__ float g_qt  [Bb * Hh];
__device__ float g_inp [Bb * Hh];
__device__ float g_att2[MCTX];
__device__ float g_colmax[Ll];
__device__ float g_colsum[Ll];
__device__ float g_logZ[Ll];
__device__ int   g_rmap[MROWS];
__device__ int   g_hv  [MROWS];
__device__ int   g_cntA;
__device__ int   g_cntB;
__device__ int   g_is64;

// ---------------- small helpers ----------------
__device__ __forceinline__ unsigned long long pack2(float x, float y) {
    unsigned long long r;
    asm("mov.b64 %0, {%1, %2};" : "=l"(r) : "r"(__float_as_uint(x)), "r"(__float_as_uint(y)));
    return r;
}
__device__ __forceinline__ float2 unpack2(unsigned long long v) {
    unsigned int lo, hi;
    asm("mov.b64 {%0, %1}, %2;" : "=r"(lo), "=r"(hi) : "l"(v));
    float2 f; f.x = __uint_as_float(lo); f.y = __uint_as_float(hi); return f;
}
#define FMA2(acc, a, b) asm("fma.rn.f32x2 %0, %1, %2, %0;" : "+l"(acc) : "l"(a), "l"(b))

__device__ __forceinline__ uint32_t rotl32(uint32_t v, int r) { return (v << r) | (v >> (32 - r)); }

// JAX Threefry-2x32-20, key = (0, 42); partitionable stream, o0^o1 fold
__device__ __forceinline__ void tf2x32(uint32_t x0, uint32_t x1, uint32_t& o0, uint32_t& o1) {
    const uint32_t k0 = 0u, k1 = 42u, k2 = 0u ^ 42u ^ 0x1BD11BDAu;
    x0 += k0; x1 += k1;
#define TFR(r) { x0 += x1; x1 = rotl32(x1, (r)); x1 ^= x0; }
    TFR(13) TFR(15) TFR(26) TFR(6)   x0 += k1; x1 += k2 + 1u;
    TFR(17) TFR(29) TFR(16) TFR(24)  x0 += k2; x1 += k0 + 2u;
    TFR(13) TFR(15) TFR(26) TFR(6)   x0 += k0; x1 += k1 + 3u;
    TFR(17) TFR(29) TFR(16) TFR(24)  x0 += k1; x1 += k2 + 4u;
    TFR(13) TFR(15) TFR(26) TFR(6)   x0 += k2; x1 += k0 + 5u;
#undef TFR
    o0 = x0; o1 = x1;
}
__device__ __forceinline__ uint32_t jax_bits(uint32_t n) {
    uint32_t o0, o1; tf2x32(0u, n, o0, o1); return o0 ^ o1;
}

// ---------------- setup kernels ----------------
__global__ void k_init() { g_cntA = 0; g_cntB = 0; }

__global__ void k_detect(const int* __restrict__ xes) {
    __shared__ int any;
    if (threadIdx.x == 0) any = 0;
    __syncthreads();
    if (xes[2 * threadIdx.x + 1] != 0) any = 1;
    __syncthreads();
    if (threadIdx.x == 0) g_is64 = !any;
}

__global__ void k_map(const int* __restrict__ xes) {
    int bt = blockIdx.x * blockDim.x + threadIdx.x;
    if (bt >= MROWS) return;
    int b = bt / TS, t = bt - b * TS;
    int base = (b * Tt + t) * 3;
    int s = g_is64 ? 2 : 1;
    int h  = xes[(base + 0) * s];
    int v  = xes[(base + 1) * s];
    int tt = xes[(base + 2) * s];
    int g;
    if (tt == 0) g = atomicAdd(&g_cntA, 1);
    else         g = MROWS - 1 - atomicAdd(&g_cntB, 1);
    g_rmap[g] = bt;
    g_hv[g]   = h | (v << 8);
}

// ---------------- edge GEMM: fused gather, 16x8 microtile, double-buffered
// 128 rows x 256 cols per block, 256 threads, K = 512 (h half then v half).
__global__ void __launch_bounds__(256, 1) k_edges(const float* __restrict__ enc,
                                                  const float* __restrict__ Wh,
                                                  const float* __restrict__ Wv,
                                                  const float* __restrict__ Wsh,
                                                  const float* __restrict__ Wsv) {
    const int row0 = blockIdx.x * 128;
    __shared__ __align__(16) float As[2][16][132];
    __shared__ __align__(16) float Bs[2][16][260];
    __shared__ const float* rpH[128];
    __shared__ const float* rpV[128];
    __shared__ int sbt[128];

    const int tid = threadIdx.x;
    if (tid < 128) {
        int g = row0 + tid;
        int bt = g_rmap[g];
        int hv = g_hv[g];
        int b = bt / TS;
        sbt[tid] = bt;
        rpH[tid] = enc + (size_t)(b * Ll + (hv & 255)) * 256;
        rpV[tid] = enc + (size_t)(b * Ll + (hv >> 8)) * 256;
    }
    __syncthreads();

    const int bound = g_cntA;
    const int tx = tid & 31, ty = tid >> 5;       // tx: 8 cols (256), ty: 16 rows (128)
    const int r0 = tid >> 2, ak = (tid & 3) * 4;  // loader mapping

    for (int pass = 0; pass < 2; pass++) {
        if (pass == 0 && row0 >= bound) continue;
        if (pass == 1 && row0 + 128 <= bound) continue;
        const float* WA = pass ? Wsh : Wh;
        const float* WB = pass ? Wsv : Wv;

        unsigned long long acc[16][4];
#pragma unroll
        for (int i = 0; i < 16; i++)
#pragma unroll
            for (int j = 0; j < 4; j++) acc[i][j] = 0ull;

        __syncthreads();   // guard smem reuse across passes

        // preload kk = 0
        float4 a_st0 = *(const float4*)(rpH[r0] + ak);
        float4 a_st1 = *(const float4*)(rpH[r0 + 64] + ak);
        float4 b_st[4];
#pragma unroll
        for (int j = 0; j < 4; j++)
            b_st[j] = *(const float4*)(WA + (size_t)(r0 + j * 64) * 256 + ak);

        for (int kk = 0; kk < 512; kk += 16) {
            const int s = (kk >> 4) & 1;
            As[s][ak + 0][r0] = a_st0.x; As[s][ak + 1][r0] = a_st0.y;
            As[s][ak + 2][r0] = a_st0.z; As[s][ak + 3][r0] = a_st0.w;
            As[s][ak + 0][r0 + 64] = a_st1.x; As[s][ak + 1][r0 + 64] = a_st1.y;
            As[s][ak + 2][r0 + 64] = a_st1.z; As[s][ak + 3][r0 + 64] = a_st1.w;
#pragma unroll
            for (int j = 0; j < 4; j++) {
                int n = r0 + j * 64;
                Bs[s][ak + 0][n] = b_st[j].x; Bs[s][ak + 1][n] = b_st[j].y;
                Bs[s][ak + 2][n] = b_st[j].z; Bs[s][ak + 3][n] = b_st[j].w;
            }
            __syncthreads();

            int kn = kk + 16;
            if (kn < 512) {
                int off = (kn & 255) + ak;
                const float* const* rp = (kn < 256) ? rpH : rpV;
                a_st0 = *(const float4*)(rp[r0] + off);
                a_st1 = *(const float4*)(rp[r0 + 64] + off);
                const float* Wp = (kn < 256) ? WA : WB;
#pragma unroll
                for (int j = 0; j < 4; j++)
                    b_st[j] = *(const float4*)(Wp + (size_t)(r0 + j * 64) * 256 + off);
            }

#pragma unroll
            for (int p = 0; p < 16; p++) {
                float4 b0 = *(const float4*)&Bs[s][p][tx * 8];
                float4 b1 = *(const float4*)&Bs[s][p][tx * 8 + 4];
                unsigned long long bb[4];
                bb[0] = pack2(b0.x, b0.y); bb[1] = pack2(b0.z, b0.w);
                bb[2] = pack2(b1.x, b1.y); bb[3] = pack2(b1.z, b1.w);
                float4 a0 = *(const float4*)&As[s][p][ty * 16];
                float4 a1 = *(const float4*)&As[s][p][ty * 16 + 4];
                float4 a2 = *(const float4*)&As[s][p][ty * 16 + 8];
                float4 a3 = *(const float4*)&As[s][p][ty * 16 + 12];
                float av[16] = {a0.x, a0.y, a0.z, a0.w, a1.x, a1.y, a1.z, a1.w,
                                a2.x, a2.y, a2.z, a2.w, a3.x, a3.y, a3.z, a3.w};
#pragma unroll
                for (int i = 0; i < 16; i++) {
                    unsigned long long aa = pack2(av[i], av[i]);
#pragma unroll
                    for (int j = 0; j < 4; j++) FMA2(acc[i][j], aa, bb[j]);
                }
            }
        }

#pragma unroll
        for (int i = 0; i < 16; i++) {
            int r = ty * 16 + i;
            int g = row0 + r;
            bool ok = (pass == 0) ? (g < bound) : (g >= bound);
            if (ok) {
                float c[8];
#pragma unroll
                for (int j = 0; j < 4; j++) {
                    float2 f = unpack2(acc[i][j]);
                    c[2 * j] = f.x; c[2 * j + 1] = f.y;
                }
                float* o = g_Edge + (size_t)sbt[r] * 256 + tx * 8;
                *(float4*)(o)     = make_float4(c[0], c[1], c[2], c[3]);
                *(float4*)(o + 4) = make_float4(c[4], c[5], c[6], c[7]);
            }
        }
    }
}

// ---------------- S GEMM fused with subtree-max + qt, double-buffered -----
__global__ void __launch_bounds__(256) k_subq(const float* __restrict__ We) {
    const int row0 = blockIdx.x * 160;
    const int col0 = blockIdx.y * 128;
    __shared__ __align__(16) float As[2][16][164];
    __shared__ __align__(16) float Bs[2][16][132];
    const int tid = threadIdx.x;
    const int tx = tid & 15, ty = tid >> 4;

    unsigned long long acc[10][4];
#pragma unroll
    for (int i = 0; i < 10; i++)
#pragma unroll
        for (int j = 0; j < 4; j++) acc[i][j] = 0ull;

    float4 a_st[3], b_st[2];
#pragma unroll
    for (int i = 0; i < 3; i++) {
        int idx = tid + i * 256;
        if (idx < 640) {
            int m = idx >> 2, kq = (idx & 3) * 4;
            a_st[i] = *(const float4*)(g_Edge + (size_t)(row0 + m) * 256 + kq);
        }
    }
#pragma unroll
    for (int i = 0; i < 2; i++) {
        int idx = tid + i * 256;
        int n = idx >> 2, kq = (idx & 3) * 4;
        b_st[i] = *(const float4*)(We + (size_t)(col0 + n) * 256 + kq);
    }

    for (int kk = 0; kk < 256; kk += 16) {
        const int s = (kk >> 4) & 1;
#pragma unroll
        for (int i = 0; i < 3; i++) {
            int idx = tid + i * 256;
            if (idx < 640) {
                int m = idx >> 2, kq = (idx & 3) * 4;
                As[s][kq + 0][m] = a_st[i].x; As[s][kq + 1][m] = a_st[i].y;
                As[s][kq + 2][m] = a_st[i].z; As[s][kq + 3][m] = a_st[i].w;
            }
        }
#pragma unroll
        for (int i = 0; i < 2; i++) {
            int idx = tid + i * 256;
            int n = idx >> 2, kq = (idx & 3) * 4;
            Bs[s][kq + 0][n] = b_st[i].x; Bs[s][kq + 1][n] = b_st[i].y;
            Bs[s][kq + 2][n] = b_st[i].z; Bs[s][kq + 3][n] = b_st[i].w;
        }
        __syncthreads();

        int kn = kk + 16;
        if (kn < 256) {
#pragma unroll
            for (int i = 0; i < 3; i++) {
                int idx = tid + i * 256;
                if (idx < 640) {
                    int m = idx >> 2, kq = (idx & 3) * 4;
                    a_st[i] = *(const float4*)(g_Edge + (size_t)(row0 + m) * 256 + kn + kq);
                }
            }
#pragma unroll
            for (int i = 0; i < 2; i++) {
                int idx = tid + i * 256;
                int n = idx >> 2, kq = (idx & 3) * 4;
                b_st[i] = *(const float4*)(We + (size_t)(col0 + n) * 256 + kn + kq);
            }
        }

#pragma unroll
        for (int p = 0; p < 16; p++) {
            float av[10];
#pragma unroll
            for (int i = 0; i < 10; i += 2) {
                float2 t2 = *(const float2*)&As[s][p][ty * 10 + i];
                av[i] = t2.x; av[i + 1] = t2.y;
            }
            float4 b0 = *(const float4*)&Bs[s][p][tx * 8];
            float4 b1 = *(const float4*)&Bs[s][p][tx * 8 + 4];
            unsigned long long bb[4];
            bb[0] = pack2(b0.x, b0.y); bb[1] = pack2(b0.z, b0.w);
            bb[2] = pack2(b1.x, b1.y); bb[3] = pack2(b1.z, b1.w);
#pragma unroll
            for (int i = 0; i < 10; i++) {
                unsigned long long aa = pack2(av[i], av[i]);
#pragma unroll
                for (int j = 0; j < 4; j++) FMA2(acc[i][j], aa, bb[j]);
            }
        }
    }

#pragma unroll
    for (int grp = 0; grp < 2; grp++) {
        int gr = row0 + ty * 10 + grp * 5;
        int b = gr / 5;
        float mx[8];
#pragma unroll
        for (int c = 0; c < 8; c++) mx[c] = 0.f;
#pragma unroll
        for (int i = 0; i < 5; i++) {
#pragma unroll
            for (int j = 0; j < 4; j++) {
                float2 f = unpack2(acc[grp * 5 + i][j]);
                mx[2 * j]     = fmaxf(mx[2 * j],     f.x);
                mx[2 * j + 1] = fmaxf(mx[2 * j + 1], f.y);
            }
        }
        const float* e4 = g_Edge + (size_t)(gr + 4) * 256 + col0 + tx * 8;
        float4 e0 = *(const float4*)(e4);
        float4 e1 = *(const float4*)(e4 + 4);
        float q[8];
        q[0] = fmaxf(e0.x + mx[0], 0.f); q[1] = fmaxf(e0.y + mx[1], 0.f);
        q[2] = fmaxf(e0.z + mx[2], 0.f); q[3] = fmaxf(e0.w + mx[3], 0.f);
        q[4] = fmaxf(e1.x + mx[4], 0.f); q[5] = fmaxf(e1.y + mx[5], 0.f);
        q[6] = fmaxf(e1.z + mx[6], 0.f); q[7] = fmaxf(e1.w + mx[7], 0.f);
        float* o = g_qt + (size_t)b * 256 + col0 + tx * 8;
        *(float4*)(o)     = make_float4(q[0], q[1], q[2], q[3]);
        *(float4*)(o + 4) = make_float4(q[4], q[5], q[6], q[7]);
    }
}

// ---------------- inp = qt @ W_in^T + b_in, double-buffered ---------------
__global__ void __launch_bounds__(256) k_inp(const float* __restrict__ Wi,
                                             const float* __restrict__ bi) {
    const int row0 = blockIdx.x * 128;
    const int col0 = blockIdx.y * 128;
    __shared__ __align__(16) float As[2][16][132];
    __shared__ __align__(16) float Bs[2][16][132];
    const int tid = threadIdx.x;
    const int tx = tid & 15, ty = tid >> 4;

    unsigned long long acc[8][4];
#pragma unroll
    for (int i = 0; i < 8; i++)
#pragma unroll
        for (int j = 0; j < 4; j++) acc[i][j] = 0ull;

    float4 a_st[2], b_st[2];
#pragma unroll
    for (int i = 0; i < 2; i++) {
        int idx = tid + i * 256;
        int m = idx >> 2, kq = (idx & 3) * 4;
        a_st[i] = *(const float4*)(g_qt + (size_t)(row0 + m) * 256 + kq);
        b_st[i] = *(const float4*)(Wi + (size_t)(col0 + m) * 256 + kq);
    }

    for (int kk = 0; kk < 256; kk += 16) {
        const int s = (kk >> 4) & 1;
#pragma unroll
        for (int i = 0; i < 2; i++) {
            int idx = tid + i * 256;
            int m = idx >> 2, kq = (idx & 3) * 4;
            As[s][kq + 0][m] = a_st[i].x; As[s][kq + 1][m] = a_st[i].y;
            As[s][kq + 2][m] = a_st[i].z; As[s][kq + 3][m] = a_st[i].w;
            Bs[s][kq + 0][m] = b_st[i].x; Bs[s][kq + 1][m] = b_st[i].y;
            Bs[s][kq + 2][m] = b_st[i].z; Bs[s][kq + 3][m] = b_st[i].w;
        }
        __syncthreads();

        int kn = kk + 16;
        if (kn < 256) {
#pragma unroll
            for (int i = 0; i < 2; i++) {
                int idx = tid + i * 256;
                int m = idx >> 2, kq = (idx & 3) * 4;
                a_st[i] = *(const float4*)(g_qt + (size_t)(row0 + m) * 256 + kn + kq);
                b_st[i] = *(const float4*)(Wi + (size_t)(col0 + m) * 256 + kn + kq);
            }
        }

#pragma unroll
        for (int p = 0; p < 16; p++) {
            float4 a0 = *(const float4*)&As[s][p][ty * 8];
            float4 a1 = *(const float4*)&As[s][p][ty * 8 + 4];
            float4 b0 = *(const float4*)&Bs[s][p][tx * 8];
            float4 b1 = *(const float4*)&Bs[s][p][tx * 8 + 4];
            unsigned long long bb[4];
            bb[0] = pack2(b0.x, b0.y); bb[1] = pack2(b0.z, b0.w);
            bb[2] = pack2(b1.x, b1.y); bb[3] = pack2(b1.z, b1.w);
            float av[8] = {a0.x, a0.y, a0.z, a0.w, a1.x, a1.y, a1.z, a1.w};
#pragma unroll
            for (int i = 0; i < 8; i++) {
                unsigned long long aa = pack2(av[i], av[i]);
#pragma unroll
                for (int j = 0; j < 4; j++) FMA2(acc[i][j], aa, bb[j]);
            }
        }
    }

#pragma unroll
    for (int i = 0; i < 8; i++) {
        int r = row0 + ty * 8 + i;
        float c[8];
#pragma unroll
        for (int j = 0; j < 4; j++) {
            float2 f = unpack2(acc[i][j]);
            c[2 * j] = f.x; c[2 * j + 1] = f.y;
        }
        const float* bp = bi + col0 + tx * 8;
#pragma unroll
        for (int j = 0; j < 8; j++) c[j] += bp[j];
        float* o = g_inp + (size_t)r * 256 + col0 + tx * 8;
        *(float4*)(o)     = make_float4(c[0], c[1], c[2], c[3]);
        *(float4*)(o + 4) = make_float4(c[4], c[5], c[6], c[7]);
    }
}

// ---------------- ctx GEMM fused with att2: 16x8, double-buffered ---------
__global__ void __launch_bounds__(256, 1) k_ctx(const float* __restrict__ A,
                                                const float* __restrict__ W,
                                                const float* __restrict__ bias,
                                                const float* __restrict__ Vv,
                                                const int* __restrict__ mask) {
    const int row0 = blockIdx.x * 128;
    __shared__ __align__(16) float As[2][16][132];
    __shared__ __align__(16) float Bs[2][16][260];
    const int tid = threadIdx.x;
    const int tx = tid & 31, ty = tid >> 5;
    const int r0 = tid >> 2, ak = (tid & 3) * 4;

    unsigned long long acc[16][4];
#pragma unroll
    for (int i = 0; i < 16; i++)
#pragma unroll
        for (int j = 0; j < 4; j++) acc[i][j] = 0ull;

    float4 a_st0 = *(const float4*)(A + (size_t)(row0 + r0) * 256 + ak);
    float4 a_st1 = *(const float4*)(A + (size_t)(row0 + r0 + 64) * 256 + ak);
    float4 b_st[4];
#pragma unroll
    for (int j = 0; j < 4; j++)
        b_st[j] = *(const float4*)(W + (size_t)(r0 + j * 64) * 256 + ak);

    for (int kk = 0; kk < 256; kk += 16) {
        const int s = (kk >> 4) & 1;
        As[s][ak + 0][r0] = a_st0.x; As[s][ak + 1][r0] = a_st0.y;
        As[s][ak + 2][r0] = a_st0.z; As[s][ak + 3][r0] = a_st0.w;
        As[s][ak + 0][r0 + 64] = a_st1.x; As[s][ak + 1][r0 + 64] = a_st1.y;
        As[s][ak + 2][r0 + 64] = a_st1.z; As[s][ak + 3][r0 + 64] = a_st1.w;
#pragma unroll
        for (int j = 0; j < 4; j++) {
            int n = r0 + j * 64;
            Bs[s][ak + 0][n] = b_st[j].x; Bs[s][ak + 1][n] = b_st[j].y;
            Bs[s][ak + 2][n] = b_st[j].z; Bs[s][ak + 3][n] = b_st[j].w;
        }
        __syncthreads();

        int kn = kk + 16;
        if (kn < 256) {
            a_st0 = *(const float4*)(A + (size_t)(row0 + r0) * 256 + kn + ak);
            a_st1 = *(const float4*)(A + (size_t)(row0 + r0 + 64) * 256 + kn + ak);
#pragma unroll
            for (int j = 0; j < 4; j++)
                b_st[j] = *(const float4*)(W + (size_t)(r0 + j * 64) * 256 + kn + ak);
        }

#pragma unroll
        for (int p = 0; p < 16; p++) {
            float4 b0 = *(const float4*)&Bs[s][p][tx * 8];
            float4 b1 = *(const float4*)&Bs[s][p][tx * 8 + 4];
            unsigned long long bb[4];
            bb[0] = pack2(b0.x, b0.y); bb[1] = pack2(b0.z, b0.w);
            bb[2] = pack2(b1.x, b1.y); bb[3] = pack2(b1.z, b1.w);
            float4 a0 = *(const float4*)&As[s][p][ty * 16];
            float4 a1 = *(const float4*)&As[s][p][ty * 16 + 4];
            float4 a2 = *(const float4*)&As[s][p][ty * 16 + 8];
            float4 a3 = *(const float4*)&As[s][p][ty * 16 + 12];
            float av[16] = {a0.x, a0.y, a0.z, a0.w, a1.x, a1.y, a1.z, a1.w,
                            a2.x, a2.y, a2.z, a2.w, a3.x, a3.y, a3.z, a3.w};
#pragma unroll
            for (int i = 0; i < 16; i++) {
                unsigned long long aa = pack2(av[i], av[i]);
#pragma unroll
                for (int j = 0; j < 4; j++) FMA2(acc[i][j], aa, bb[j]);
            }
        }
    }

    float bc[8], vv[8];
#pragma unroll
    for (int j = 0; j < 8; j++) { bc[j] = bias[tx * 8 + j]; vv[j] = Vv[tx * 8 + j]; }

#pragma unroll
    for (int i = 0; i < 16; i++) {
        int m = row0 + ty * 16 + i;
        int b = m / Ll;
        const float* ip = g_inp + (size_t)b * 256 + tx * 8;
        float s = 0.f;
#pragma unroll
        for (int j = 0; j < 4; j++) {
            float2 cf = unpack2(acc[i][j]);
            int jj = 2 * j;
            s += vv[jj]     * tanhf(ip[jj]     + (cf.x + bc[jj]));
            s += vv[jj + 1] * tanhf(ip[jj + 1] + (cf.y + bc[jj + 1]));
        }
#pragma unroll
        for (int o = 16; o > 0; o >>= 1) s += __shfl_xor_sync(0xffffffffu, s, o);
        if (tx == 0) {
            if (mask[m] == 0) s = -1000000000.0f;
            g_att2[m] = 10.0f * tanhf(s);
        }
    }
}

// ---------------- per-column softmax stats over batch axis ----------------
__global__ void k_colred() {
    const int l = blockIdx.x;
    __shared__ float red[256];
    float mx = __int_as_float(0xff800000);
    for (int b = threadIdx.x; b < Bb; b += 256) mx = fmaxf(mx, g_att2[b * Ll + l]);
    red[threadIdx.x] = mx; __syncthreads();
    for (int o = 128; o > 0; o >>= 1) {
        if (threadIdx.x < o) red[threadIdx.x] = fmaxf(red[threadIdx.x], red[threadIdx.x + o]);
        __syncthreads();
    }
    mx = red[0]; __syncthreads();
    float sum = 0.f;
    for (int b = threadIdx.x; b < Bb; b += 256) sum += expf(g_att2[b * Ll + l] - mx);
    red[threadIdx.x] = sum; __syncthreads();
    for (int o = 128; o > 0; o >>= 1) {
        if (threadIdx.x < o) red[threadIdx.x] += red[threadIdx.x + o];
        __syncthreads();
    }
    if (threadIdx.x == 0) {
        g_colmax[l] = mx;
        g_colsum[l] = red[0];
        g_logZ[l]   = mx + logf(red[0]);
    }
}

// ---------------- Gumbel-argmax + p + new_mask ----------------------------
__global__ void k_final(const int* __restrict__ mask, float* __restrict__ out) {
    int b = blockIdx.x * blockDim.x + threadIdx.x;
    if (b >= Bb) return;
    const float TINY = 1.17549435e-38f;
    float best = __int_as_float(0xff800000);
    int idx = 0;
    float a2[Ll];
#pragma unroll
    for (int l = 0; l < Ll; l++) {
        float a = g_att2[b * Ll + l];
        a2[l] = a;
        float la = a - g_logZ[l];
        uint32_t bits = jax_bits((uint32_t)(b * Ll + l));
        float fl = __uint_as_float((bits >> 9) | 0x3F800000u) - 1.0f;
        float u  = fmaxf(TINY, fl + TINY);
        float g  = -logf(-logf(u));
        float s  = la + g;
        if (s > best) { best = s; idx = l; }
    }
    float p = expf(a2[idx] - g_colmax[idx]) / g_colsum[idx];
    out[b]      = (float)idx;
    out[Bb + b] = p;
#pragma unroll
    for (int l = 0; l < Ll; l++)
        out[2 * Bb + b * Ll + l] = (float)(mask[b * Ll + l] - (l == idx ? 1 : 0));
}

// ---------------- launcher ----------------
extern "C" void kernel_launch(void* const* d_in, const int* in_sizes, int n_in,
                              void* d_out, int out_size) {
    const float* enc    = (const float*)d_in[0];
    const int*   xes    = (const int*)  d_in[1];
    const int*   mask   = (const int*)  d_in[2];
    const float* W_h    = (const float*)d_in[3];
    const float* W_v    = (const float*)d_in[4];
    const float* Ws_h   = (const float*)d_in[5];
    const float* Ws_v   = (const float*)d_in[6];
    const float* W_edge = (const float*)d_in[7];
    const float* W_in   = (const float*)d_in[8];
    const float* b_in   = (const float*)d_in[9];
    const float* W_ctx  = (const float*)d_in[10];
    const float* b_ctx  = (const float*)d_in[11];
    const float* Vv     = (const float*)d_in[12];
    float* out = (float*)d_out;

    k_init<<<1, 1>>>();
    k_detect<<<1, 128>>>(xes);
    k_map<<<(MROWS + 255) / 256, 256>>>(xes);

    k_edges<<<MROWS / 128, 256>>>(enc, W_h, W_v, Ws_h, Ws_v);
    k_subq<<<dim3(MROWS / 160, 2), 256>>>(W_edge);
    k_inp<<<dim3(Bb / 128, 2), 256>>>(W_in, b_in);
    k_ctx<<<MCTX / 128, 256>>>(enc, W_ctx, b_ctx, Vv, mask);
    k_colred<<<Ll, 256>>>();
    k_final<<<(Bb + 255) / 256, 256>>>(mask, out);
}

// round 11
// speedup vs baseline: 1.0032x; 1.0032x over previous
#include <cuda_runtime.h>
#include <stdint.h>

// Problem constants
#define Bb    32768
#define Ll    7
#define Tt    6
#define Hh    256
#define TS    5                 // only edges t=0..4 are live
#define MROWS (Bb * TS)         // 163840
#define MCTX  (Bb * Ll)         // 229376

// ---------------- device scratch (static, allocation-free) ----------------
__device__ float g_Edge[(size_t)MROWS * Hh];
__device__ float g_qt  [Bb * Hh];
__device__ float g_inp [Bb * Hh];
__device__ float g_att2[MCTX];
__device__ float g_colmax[Ll];
__device__ float g_colsum[Ll];
__device__ float g_logZ[Ll];
__device__ int   g_rmap[MROWS];
__device__ int   g_hv  [MROWS];
__device__ int   g_cntA;
__device__ int   g_cntB;
__device__ int   g_is64;

// ---------------- small helpers ----------------
__device__ __forceinline__ unsigned long long pack2(float x, float y) {
    unsigned long long r;
    asm("mov.b64 %0, {%1, %2};" : "=l"(r) : "r"(__float_as_uint(x)), "r"(__float_as_uint(y)));
    return r;
}
__device__ __forceinline__ float2 unpack2(unsigned long long v) {
    unsigned int lo, hi;
    asm("mov.b64 {%0, %1}, %2;" : "=r"(lo), "=r"(hi) : "l"(v));
    float2 f; f.x = __uint_as_float(lo); f.y = __uint_as_float(hi); return f;
}
#define FMA2(acc, a, b) asm("fma.rn.f32x2 %0, %1, %2, %0;" : "+l"(acc) : "l"(a), "l"(b))

__device__ __forceinline__ uint32_t rotl32(uint32_t v, int r) { return (v << r) | (v >> (32 - r)); }

// JAX Threefry-2x32-20, key = (0, 42); partitionable stream, o0^o1 fold
__device__ __forceinline__ void tf2x32(uint32_t x0, uint32_t x1, uint32_t& o0, uint32_t& o1) {
    const uint32_t k0 = 0u, k1 = 42u, k2 = 0u ^ 42u ^ 0x1BD11BDAu;
    x0 += k0; x1 += k1;
#define TFR(r) { x0 += x1; x1 = rotl32(x1, (r)); x1 ^= x0; }
    TFR(13) TFR(15) TFR(26) TFR(6)   x0 += k1; x1 += k2 + 1u;
    TFR(17) TFR(29) TFR(16) TFR(24)  x0 += k2; x1 += k0 + 2u;
    TFR(13) TFR(15) TFR(26) TFR(6)   x0 += k0; x1 += k1 + 3u;
    TFR(17) TFR(29) TFR(16) TFR(24)  x0 += k1; x1 += k2 + 4u;
    TFR(13) TFR(15) TFR(26) TFR(6)   x0 += k2; x1 += k0 + 5u;
#undef TFR
    o0 = x0; o1 = x1;
}
__device__ __forceinline__ uint32_t jax_bits(uint32_t n) {
    uint32_t o0, o1; tf2x32(0u, n, o0, o1); return o0 ^ o1;
}

// ---------------- setup kernels ----------------
__global__ void k_init() { g_cntA = 0; g_cntB = 0; }

__global__ void k_detect(const int* __restrict__ xes) {
    __shared__ int any;
    if (threadIdx.x == 0) any = 0;
    __syncthreads();
    if (xes[2 * threadIdx.x + 1] != 0) any = 1;
    __syncthreads();
    if (threadIdx.x == 0) g_is64 = !any;
}

__global__ void k_map(const int* __restrict__ xes) {
    int bt = blockIdx.x * blockDim.x + threadIdx.x;
    if (bt >= MROWS) return;
    int b = bt / TS, t = bt - b * TS;
    int base = (b * Tt + t) * 3;
    int s = g_is64 ? 2 : 1;
    int h  = xes[(base + 0) * s];
    int v  = xes[(base + 1) * s];
    int tt = xes[(base + 2) * s];
    int g;
    if (tt == 0) g = atomicAdd(&g_cntA, 1);
    else         g = MROWS - 1 - atomicAdd(&g_cntB, 1);
    g_rmap[g] = bt;
    g_hv[g]   = h | (v << 8);
}

// ---------------- edge GEMM: fused gather, 8x8 microtile, 4 warps/SMSP ----
// 128 rows x 128 cols per block (grid.y = col half), 256 threads, K = 512.
__global__ void __launch_bounds__(256, 2) k_edges(const float* __restrict__ enc,
                                                  const float* __restrict__ Wh,
                                                  const float* __restrict__ Wv,
                                                  const float* __restrict__ Wsh,
                                                  const float* __restrict__ Wsv) {
    const int row0 = blockIdx.x * 128;
    const int col0 = blockIdx.y * 128;
    __shared__ __align__(16) float As[2][16][132];
    __shared__ __align__(16) float Bs[2][16][132];
    __shared__ const float* rpH[128];
    __shared__ const float* rpV[128];
    __shared__ int sbt[128];

    const int tid = threadIdx.x;
    if (tid < 128) {
        int g = row0 + tid;
        int bt = g_rmap[g];
        int hv = g_hv[g];
        int b = bt / TS;
        sbt[tid] = bt;
        rpH[tid] = enc + (size_t)(b * Ll + (hv & 255)) * 256;
        rpV[tid] = enc + (size_t)(b * Ll + (hv >> 8)) * 256;
    }
    __syncthreads();

    const int bound = g_cntA;
    const int tx = tid & 15, ty = tid >> 4;       // 8 cols, 8 rows per thread

    for (int pass = 0; pass < 2; pass++) {
        if (pass == 0 && row0 >= bound) continue;
        if (pass == 1 && row0 + 128 <= bound) continue;
        const float* WA = pass ? Wsh : Wh;
        const float* WB = pass ? Wsv : Wv;

        unsigned long long acc[8][4];
#pragma unroll
        for (int i = 0; i < 8; i++)
#pragma unroll
            for (int j = 0; j < 4; j++) acc[i][j] = 0ull;

        __syncthreads();   // guard smem reuse across passes

        // preload kk = 0  (2 float4 each for A and B)
        float4 a_st[2], b_st[2];
#pragma unroll
        for (int i = 0; i < 2; i++) {
            int idx = tid + i * 256;
            int m = idx >> 2, kq = (idx & 3) * 4;
            a_st[i] = *(const float4*)(rpH[m] + kq);
            b_st[i] = *(const float4*)(WA + (size_t)(col0 + m) * 256 + kq);
        }

        for (int kk = 0; kk < 512; kk += 16) {
            const int s = (kk >> 4) & 1;
#pragma unroll
            for (int i = 0; i < 2; i++) {
                int idx = tid + i * 256;
                int m = idx >> 2, kq = (idx & 3) * 4;
                As[s][kq + 0][m] = a_st[i].x; As[s][kq + 1][m] = a_st[i].y;
                As[s][kq + 2][m] = a_st[i].z; As[s][kq + 3][m] = a_st[i].w;
                Bs[s][kq + 0][m] = b_st[i].x; Bs[s][kq + 1][m] = b_st[i].y;
                Bs[s][kq + 2][m] = b_st[i].z; Bs[s][kq + 3][m] = b_st[i].w;
            }
            __syncthreads();

            int kn = kk + 16;
            if (kn < 512) {
                int off = (kn & 255);
                const float* const* rp = (kn < 256) ? rpH : rpV;
                const float* Wp = (kn < 256) ? WA : WB;
#pragma unroll
                for (int i = 0; i < 2; i++) {
                    int idx = tid + i * 256;
                    int m = idx >> 2, kq = (idx & 3) * 4;
                    a_st[i] = *(const float4*)(rp[m] + off + kq);
                    b_st[i] = *(const float4*)(Wp + (size_t)(col0 + m) * 256 + off + kq);
                }
            }

#pragma unroll
            for (int p = 0; p < 16; p++) {
                float4 a0 = *(const float4*)&As[s][p][ty * 8];
                float4 a1 = *(const float4*)&As[s][p][ty * 8 + 4];
                float4 b0 = *(const float4*)&Bs[s][p][tx * 8];
                float4 b1 = *(const float4*)&Bs[s][p][tx * 8 + 4];
                unsigned long long bb[4];
                bb[0] = pack2(b0.x, b0.y); bb[1] = pack2(b0.z, b0.w);
                bb[2] = pack2(b1.x, b1.y); bb[3] = pack2(b1.z, b1.w);
                float av[8] = {a0.x, a0.y, a0.z, a0.w, a1.x, a1.y, a1.z, a1.w};
#pragma unroll
                for (int i = 0; i < 8; i++) {
                    unsigned long long aa = pack2(av[i], av[i]);
#pragma unroll
                    for (int j = 0; j < 4; j++) FMA2(acc[i][j], aa, bb[j]);
                }
            }
        }

#pragma unroll
        for (int i = 0; i < 8; i++) {
            int r = ty * 8 + i;
            int g = row0 + r;
            bool ok = (pass == 0) ? (g < bound) : (g >= bound);
            if (ok) {
                float c[8];
#pragma unroll
                for (int j = 0; j < 4; j++) {
                    float2 f = unpack2(acc[i][j]);
                    c[2 * j] = f.x; c[2 * j + 1] = f.y;
                }
                float* o = g_Edge + (size_t)sbt[r] * 256 + col0 + tx * 8;
                *(float4*)(o)     = make_float4(c[0], c[1], c[2], c[3]);
                *(float4*)(o + 4) = make_float4(c[4], c[5], c[6], c[7]);
            }
        }
    }
}

// ---------------- S GEMM fused with subtree-max + qt (unchanged) ----------
__global__ void __launch_bounds__(256) k_subq(const float* __restrict__ We) {
    const int row0 = blockIdx.x * 160;
    const int col0 = blockIdx.y * 128;
    __shared__ __align__(16) float As[2][16][164];
    __shared__ __align__(16) float Bs[2][16][132];
    const int tid = threadIdx.x;
    const int tx = tid & 15, ty = tid >> 4;

    unsigned long long acc[10][4];
#pragma unroll
    for (int i = 0; i < 10; i++)
#pragma unroll
        for (int j = 0; j < 4; j++) acc[i][j] = 0ull;

    float4 a_st[3], b_st[2];
#pragma unroll
    for (int i = 0; i < 3; i++) {
        int idx = tid + i * 256;
        if (idx < 640) {
            int m = idx >> 2, kq = (idx & 3) * 4;
            a_st[i] = *(const float4*)(g_Edge + (size_t)(row0 + m) * 256 + kq);
        }
    }
#pragma unroll
    for (int i = 0; i < 2; i++) {
        int idx = tid + i * 256;
        int n = idx >> 2, kq = (idx & 3) * 4;
        b_st[i] = *(const float4*)(We + (size_t)(col0 + n) * 256 + kq);
    }

    for (int kk = 0; kk < 256; kk += 16) {
        const int s = (kk >> 4) & 1;
#pragma unroll
        for (int i = 0; i < 3; i++) {
            int idx = tid + i * 256;
            if (idx < 640) {
                int m = idx >> 2, kq = (idx & 3) * 4;
                As[s][kq + 0][m] = a_st[i].x; As[s][kq + 1][m] = a_st[i].y;
                As[s][kq + 2][m] = a_st[i].z; As[s][kq + 3][m] = a_st[i].w;
            }
        }
#pragma unroll
        for (int i = 0; i < 2; i++) {
            int idx = tid + i * 256;
            int n = idx >> 2, kq = (idx & 3) * 4;
            Bs[s][kq + 0][n] = b_st[i].x; Bs[s][kq + 1][n] = b_st[i].y;
            Bs[s][kq + 2][n] = b_st[i].z; Bs[s][kq + 3][n] = b_st[i].w;
        }
        __syncthreads();

        int kn = kk + 16;
        if (kn < 256) {
#pragma unroll
            for (int i = 0; i < 3; i++) {
                int idx = tid + i * 256;
                if (idx < 640) {
                    int m = idx >> 2, kq = (idx & 3) * 4;
                    a_st[i] = *(const float4*)(g_Edge + (size_t)(row0 + m) * 256 + kn + kq);
                }
            }
#pragma unroll
            for (int i = 0; i < 2; i++) {
                int idx = tid + i * 256;
                int n = idx >> 2, kq = (idx & 3) * 4;
                b_st[i] = *(const float4*)(We + (size_t)(col0 + n) * 256 + kn + kq);
            }
        }

#pragma unroll
        for (int p = 0; p < 16; p++) {
            float av[10];
#pragma unroll
            for (int i = 0; i < 10; i += 2) {
                float2 t2 = *(const float2*)&As[s][p][ty * 10 + i];
                av[i] = t2.x; av[i + 1] = t2.y;
            }
            float4 b0 = *(const float4*)&Bs[s][p][tx * 8];
            float4 b1 = *(const float4*)&Bs[s][p][tx * 8 + 4];
            unsigned long long bb[4];
            bb[0] = pack2(b0.x, b0.y); bb[1] = pack2(b0.z, b0.w);
            bb[2] = pack2(b1.x, b1.y); bb[3] = pack2(b1.z, b1.w);
#pragma unroll
            for (int i = 0; i < 10; i++) {
                unsigned long long aa = pack2(av[i], av[i]);
#pragma unroll
                for (int j = 0; j < 4; j++) FMA2(acc[i][j], aa, bb[j]);
            }
        }
    }

#pragma unroll
    for (int grp = 0; grp < 2; grp++) {
        int gr = row0 + ty * 10 + grp * 5;
        int b = gr / 5;
        float mx[8];
#pragma unroll
        for (int c = 0; c < 8; c++) mx[c] = 0.f;
#pragma unroll
        for (int i = 0; i < 5; i++) {
#pragma unroll
            for (int j = 0; j < 4; j++) {
                float2 f = unpack2(acc[grp * 5 + i][j]);
                mx[2 * j]     = fmaxf(mx[2 * j],     f.x);
                mx[2 * j + 1] = fmaxf(mx[2 * j + 1], f.y);
            }
        }
        const float* e4 = g_Edge + (size_t)(gr + 4) * 256 + col0 + tx * 8;
        float4 e0 = *(const float4*)(e4);
        float4 e1 = *(const float4*)(e4 + 4);
        float q[8];
        q[0] = fmaxf(e0.x + mx[0], 0.f); q[1] = fmaxf(e0.y + mx[1], 0.f);
        q[2] = fmaxf(e0.z + mx[2], 0.f); q[3] = fmaxf(e0.w + mx[3], 0.f);
        q[4] = fmaxf(e1.x + mx[4], 0.f); q[5] = fmaxf(e1.y + mx[5], 0.f);
        q[6] = fmaxf(e1.z + mx[6], 0.f); q[7] = fmaxf(e1.w + mx[7], 0.f);
        float* o = g_qt + (size_t)b * 256 + col0 + tx * 8;
        *(float4*)(o)     = make_float4(q[0], q[1], q[2], q[3]);
        *(float4*)(o + 4) = make_float4(q[4], q[5], q[6], q[7]);
    }
}

// ---------------- inp = qt @ W_in^T + b_in (unchanged) --------------------
__global__ void __launch_bounds__(256) k_inp(const float* __restrict__ Wi,
                                             const float* __restrict__ bi) {
    const int row0 = blockIdx.x * 128;
    const int col0 = blockIdx.y * 128;
    __shared__ __align__(16) float As[2][16][132];
    __shared__ __align__(16) float Bs[2][16][132];
    const int tid = threadIdx.x;
    const int tx = tid & 15, ty = tid >> 4;

    unsigned long long acc[8][4];
#pragma unroll
    for (int i = 0; i < 8; i++)
#pragma unroll
        for (int j = 0; j < 4; j++) acc[i][j] = 0ull;

    float4 a_st[2], b_st[2];
#pragma unroll
    for (int i = 0; i < 2; i++) {
        int idx = tid + i * 256;
        int m = idx >> 2, kq = (idx & 3) * 4;
        a_st[i] = *(const float4*)(g_qt + (size_t)(row0 + m) * 256 + kq);
        b_st[i] = *(const float4*)(Wi + (size_t)(col0 + m) * 256 + kq);
    }

    for (int kk = 0; kk < 256; kk += 16) {
        const int s = (kk >> 4) & 1;
#pragma unroll
        for (int i = 0; i < 2; i++) {
            int idx = tid + i * 256;
            int m = idx >> 2, kq = (idx & 3) * 4;
            As[s][kq + 0][m] = a_st[i].x; As[s][kq + 1][m] = a_st[i].y;
            As[s][kq + 2][m] = a_st[i].z; As[s][kq + 3][m] = a_st[i].w;
            Bs[s][kq + 0][m] = b_st[i].x; Bs[s][kq + 1][m] = b_st[i].y;
            Bs[s][kq + 2][m] = b_st[i].z; Bs[s][kq + 3][m] = b_st[i].w;
        }
        __syncthreads();

        int kn = kk + 16;
        if (kn < 256) {
#pragma unroll
            for (int i = 0; i < 2; i++) {
                int idx = tid + i * 256;
                int m = idx >> 2, kq = (idx & 3) * 4;
                a_st[i] = *(const float4*)(g_qt + (size_t)(row0 + m) * 256 + kn + kq);
                b_st[i] = *(const float4*)(Wi + (size_t)(col0 + m) * 256 + kn + kq);
            }
        }

#pragma unroll
        for (int p = 0; p < 16; p++) {
            float4 a0 = *(const float4*)&As[s][p][ty * 8];
            float4 a1 = *(const float4*)&As[s][p][ty * 8 + 4];
            float4 b0 = *(const float4*)&Bs[s][p][tx * 8];
            float4 b1 = *(const float4*)&Bs[s][p][tx * 8 + 4];
            unsigned long long bb[4];
            bb[0] = pack2(b0.x, b0.y); bb[1] = pack2(b0.z, b0.w);
            bb[2] = pack2(b1.x, b1.y); bb[3] = pack2(b1.z, b1.w);
            float av[8] = {a0.x, a0.y, a0.z, a0.w, a1.x, a1.y, a1.z, a1.w};
#pragma unroll
            for (int i = 0; i < 8; i++) {
                unsigned long long aa = pack2(av[i], av[i]);
#pragma unroll
                for (int j = 0; j < 4; j++) FMA2(acc[i][j], aa, bb[j]);
            }
        }
    }

#pragma unroll
    for (int i = 0; i < 8; i++) {
        int r = row0 + ty * 8 + i;
        float c[8];
#pragma unroll
        for (int j = 0; j < 4; j++) {
            float2 f = unpack2(acc[i][j]);
            c[2 * j] = f.x; c[2 * j + 1] = f.y;
        }
        const float* bp = bi + col0 + tx * 8;
#pragma unroll
        for (int j = 0; j < 8; j++) c[j] += bp[j];
        float* o = g_inp + (size_t)r * 256 + col0 + tx * 8;
        *(float4*)(o)     = make_float4(c[0], c[1], c[2], c[3]);
        *(float4*)(o + 4) = make_float4(c[4], c[5], c[6], c[7]);
    }
}

// ---------------- ctx GEMM fused with att2: 8x8 microtile, 512 threads ----
// 128 rows x 256 cols per block; warp lane spans the 256 cols (row reduce).
__global__ void __launch_bounds__(512, 1) k_ctx(const float* __restrict__ A,
                                                const float* __restrict__ W,
                                                const float* __restrict__ bias,
                                                const float* __restrict__ Vv,
                                                const int* __restrict__ mask) {
    const int row0 = blockIdx.x * 128;
    __shared__ __align__(16) float As[2][16][132];
    __shared__ __align__(16) float Bs[2][16][260];
    const int tid = threadIdx.x;
    const int lane = tid & 31, w = tid >> 5;      // w: 16 row-groups of 8

    unsigned long long acc[8][4];
#pragma unroll
    for (int i = 0; i < 8; i++)
#pragma unroll
        for (int j = 0; j < 4; j++) acc[i][j] = 0ull;

    const int am = tid >> 2, ak = (tid & 3) * 4;  // A: am 0..127 (1 f4 each)
    float4 a_st = *(const float4*)(A + (size_t)(row0 + am) * 256 + ak);
    float4 b_st[2];
#pragma unroll
    for (int i = 0; i < 2; i++) {
        int idx = tid + i * 512;
        int n = idx >> 2, kq = (idx & 3) * 4;
        b_st[i] = *(const float4*)(W + (size_t)n * 256 + kq);
    }

    for (int kk = 0; kk < 256; kk += 16) {
        const int s = (kk >> 4) & 1;
        As[s][ak + 0][am] = a_st.x; As[s][ak + 1][am] = a_st.y;
        As[s][ak + 2][am] = a_st.z; As[s][ak + 3][am] = a_st.w;
#pragma unroll
        for (int i = 0; i < 2; i++) {
            int idx = tid + i * 512;
            int n = idx >> 2, kq = (idx & 3) * 4;
            Bs[s][kq + 0][n] = b_st[i].x; Bs[s][kq + 1][n] = b_st[i].y;
            Bs[s][kq + 2][n] = b_st[i].z; Bs[s][kq + 3][n] = b_st[i].w;
        }
        __syncthreads();

        int kn = kk + 16;
        if (kn < 256) {
            a_st = *(const float4*)(A + (size_t)(row0 + am) * 256 + kn + ak);
#pragma unroll
            for (int i = 0; i < 2; i++) {
                int idx = tid + i * 512;
                int n = idx >> 2, kq = (idx & 3) * 4;
                b_st[i] = *(const float4*)(W + (size_t)n * 256 + kn + kq);
            }
        }

#pragma unroll
        for (int p = 0; p < 16; p++) {
            float4 a0 = *(const float4*)&As[s][p][w * 8];
            float4 a1 = *(const float4*)&As[s][p][w * 8 + 4];
            float4 b0 = *(const float4*)&Bs[s][p][lane * 8];
            float4 b1 = *(const float4*)&Bs[s][p][lane * 8 + 4];
            unsigned long long bb[4];
            bb[0] = pack2(b0.x, b0.y); bb[1] = pack2(b0.z, b0.w);
            bb[2] = pack2(b1.x, b1.y); bb[3] = pack2(b1.z, b1.w);
            float av[8] = {a0.x, a0.y, a0.z, a0.w, a1.x, a1.y, a1.z, a1.w};
#pragma unroll
            for (int i = 0; i < 8; i++) {
                unsigned long long aa = pack2(av[i], av[i]);
#pragma unroll
                for (int j = 0; j < 4; j++) FMA2(acc[i][j], aa, bb[j]);
            }
        }
    }

    float bc[8], vv[8];
#pragma unroll
    for (int j = 0; j < 8; j++) { bc[j] = bias[lane * 8 + j]; vv[j] = Vv[lane * 8 + j]; }

#pragma unroll
    for (int i = 0; i < 8; i++) {
        int m = row0 + w * 8 + i;
        int b = m / Ll;
        const float* ip = g_inp + (size_t)b * 256 + lane * 8;
        float s = 0.f;
#pragma unroll
        for (int j = 0; j < 4; j++) {
            float2 cf = unpack2(acc[i][j]);
            int jj = 2 * j;
            s += vv[jj]     * tanhf(ip[jj]     + (cf.x + bc[jj]));
            s += vv[jj + 1] * tanhf(ip[jj + 1] + (cf.y + bc[jj + 1]));
        }
#pragma unroll
        for (int o = 16; o > 0; o >>= 1) s += __shfl_xor_sync(0xffffffffu, s, o);
        if (lane == 0) {
            if (mask[m] == 0) s = -1000000000.0f;
            g_att2[m] = 10.0f * tanhf(s);
        }
    }
}

// ---------------- per-column softmax stats over batch axis ----------------
__global__ void k_colred() {
    const int l = blockIdx.x;
    __shared__ float red[256];
    float mx = __int_as_float(0xff800000);
    for (int b = threadIdx.x; b < Bb; b += 256) mx = fmaxf(mx, g_att2[b * Ll + l]);
    red[threadIdx.x] = mx; __syncthreads();
    for (int o = 128; o > 0; o >>= 1) {
        if (threadIdx.x < o) red[threadIdx.x] = fmaxf(red[threadIdx.x], red[threadIdx.x + o]);
        __syncthreads();
    }
    mx = red[0]; __syncthreads();
    float sum = 0.f;
    for (int b = threadIdx.x; b < Bb; b += 256) sum += expf(g_att2[b * Ll + l] - mx);
    red[threadIdx.x] = sum; __syncthreads();
    for (int o = 128; o > 0; o >>= 1) {
        if (threadIdx.x < o) red[threadIdx.x] += red[threadIdx.x + o];
        __syncthreads();
    }
    if (threadIdx.x == 0) {
        g_colmax[l] = mx;
        g_colsum[l] = red[0];
        g_logZ[l]   = mx + logf(red[0]);
    }
}

// ---------------- Gumbel-argmax + p + new_mask ----------------------------
__global__ void k_final(const int* __restrict__ mask, float* __restrict__ out) {
    int b = blockIdx.x * blockDim.x + threadIdx.x;
    if (b >= Bb) return;
    const float TINY = 1.17549435e-38f;
    float best = __int_as_float(0xff800000);
    int idx = 0;
    float a2[Ll];
#pragma unroll
    for (int l = 0; l < Ll; l++) {
        float a = g_att2[b * Ll + l];
        a2[l] = a;
        float la = a - g_logZ[l];
        uint32_t bits = jax_bits((uint32_t)(b * Ll + l));
        float fl = __uint_as_float((bits >> 9) | 0x3F800000u) - 1.0f;
        float u  = fmaxf(TINY, fl + TINY);
        float g  = -logf(-logf(u));
        float s  = la + g;
        if (s > best) { best = s; idx = l; }
    }
    float p = expf(a2[idx] - g_colmax[idx]) / g_colsum[idx];
    out[b]      = (float)idx;
    out[Bb + b] = p;
#pragma unroll
    for (int l = 0; l < Ll; l++)
        out[2 * Bb + b * Ll + l] = (float)(mask[b * Ll + l] - (l == idx ? 1 : 0));
}

// ---------------- launcher ----------------
extern "C" void kernel_launch(void* const* d_in, const int* in_sizes, int n_in,
                              void* d_out, int out_size) {
    const float* enc    = (const float*)d_in[0];
    const int*   xes    = (const int*)  d_in[1];
    const int*   mask   = (const int*)  d_in[2];
    const float* W_h    = (const float*)d_in[3];
    const float* W_v    = (const float*)d_in[4];
    const float* Ws_h   = (const float*)d_in[5];
    const float* Ws_v   = (const float*)d_in[6];
    const float* W_edge = (const float*)d_in[7];
    const float* W_in   = (const float*)d_in[8];
    const float* b_in   = (const float*)d_in[9];
    const float* W_ctx  = (const float*)d_in[10];
    const float* b_ctx  = (const float*)d_in[11];
    const float* Vv     = (const float*)d_in[12];
    float* out = (float*)d_out;

    k_init<<<1, 1>>>();
    k_detect<<<1, 128>>>(xes);
    k_map<<<(MROWS + 255) / 256, 256>>>(xes);

    k_edges<<<dim3(MROWS / 128, 2), 256>>>(enc, W_h, W_v, Ws_h, Ws_v);
    k_subq<<<dim3(MROWS / 160, 2), 256>>>(W_edge);
    k_inp<<<dim3(Bb / 128, 2), 256>>>(W_in, b_in);
    k_ctx<<<MCTX / 128, 512>>>(enc, W_ctx, b_ctx, Vv, mask);
    k_colred<<<Ll, 256>>>();
    k_final<<<(Bb + 255) / 256, 256>>>(mask, out);
}